// round 4
// baseline (speedup 1.0000x reference)
#include <cuda_runtime.h>
#include <stdint.h>

#define D 128
#define MAX_NODES 50000
#define MAX_EDGES 800000
#define BM 128
#define SCAN_T 256

typedef unsigned long long ull;

// ---- device scratch (no allocations allowed) ----
__device__ float g_support[(size_t)MAX_NODES * D];   // x @ W
__device__ int   g_cursor[MAX_NODES];                // counts -> starts -> ends
__device__ int   g_bsum[(MAX_NODES + SCAN_T - 1) / SCAN_T];
__device__ int   g_boff[(MAX_NODES + SCAN_T - 1) / SCAN_T];
__device__ int   g_scol[MAX_EDGES];
__device__ float g_sw[MAX_EDGES];
__device__ int   g_idx64;

// ---- packed f32x2 helpers (FFMA2 — ptxas never auto-emits this) ----
__device__ __forceinline__ ull bc2(float v) {
    ull r; asm("mov.b64 %0, {%1, %1};" : "=l"(r) : "f"(v)); return r;
}
__device__ __forceinline__ void fma2(ull& d, ull a, ull b) {
    asm("fma.rn.f32x2 %0, %1, %2, %3;" : "=l"(d) : "l"(a), "l"(b), "l"(d));
}
__device__ __forceinline__ void upk2(float& lo, float& hi, ull p) {
    asm("mov.b64 {%0, %1}, %2;" : "=f"(lo), "=f"(hi) : "l"(p));
}

// ---------------------------------------------------------------------------
__global__ void detect_idx_kernel(const void* idx) {
    const ull* p = (const ull*)idx;
    int is64 = 1;
    #pragma unroll
    for (int i = 0; i < 16; i++)
        if (p[i] >= (1ULL << 32)) is64 = 0;
    g_idx64 = is64;
}

__device__ __forceinline__ int load_idx(const void* buf, int e) {
    return g_idx64 ? (int)((const long long*)buf)[e] : ((const int*)buf)[e];
}

// ---------------------------------------------------------------------------
// SGEMM with packed f32x2 FMAs: support[M,128] = x[M,128] @ W[128,128]
// 256 threads/block, 128 rows/block. Micro-tile: 8 rows x 8 cols per thread,
// held as 4 row-pairs x 8 cols of f32x2 accumulators.
// Thread tx covers cols [4tx,4tx+4) and [4tx+64,4tx+68)  (conflict-free LDS).
// ---------------------------------------------------------------------------
__global__ void __launch_bounds__(256, 1)
gemm_kernel(const float* __restrict__ x, const float* __restrict__ w, int M) {
    extern __shared__ float sm[];
    float* Wsh = sm;                 // [128][128]
    float* Ash = sm + D * D;         // [132][?]: Ash[k*132 + r]  (A transposed)
    const int AS = 132;

    const int tid  = threadIdx.x;
    const int row0 = blockIdx.x * BM;

    #pragma unroll
    for (int i = tid; i < (D * D) / 4; i += 256)
        ((float4*)Wsh)[i] = ((const float4*)w)[i];

    #pragma unroll
    for (int l = 0; l < 16; l++) {
        int f = tid + 256 * l;
        int r = f >> 5;
        int q = f & 31;
        int k = q * 4;
        float4 v = make_float4(0.f, 0.f, 0.f, 0.f);
        int gr = row0 + r;
        if (gr < M) v = ((const float4*)(x + (size_t)gr * D))[q];
        Ash[(k + 0) * AS + r] = v.x;
        Ash[(k + 1) * AS + r] = v.y;
        Ash[(k + 2) * AS + r] = v.z;
        Ash[(k + 3) * AS + r] = v.w;
    }
    __syncthreads();

    const int tx = tid & 15, ty = tid >> 4;
    const int rbase = ty * 8;
    const int c1 = tx * 4;
    const int c2 = tx * 4 + 64;

    ull acc[4][8];
    #pragma unroll
    for (int i = 0; i < 4; i++)
        #pragma unroll
        for (int j = 0; j < 8; j++) acc[i][j] = 0ULL;

    #pragma unroll 4
    for (int k = 0; k < D; k++) {
        // a: 8 consecutive rows -> 4 natural f32x2 pairs (64-bit aligned)
        const ull* arow = (const ull*)&Ash[k * AS + rbase];
        ull ap0 = arow[0], ap1 = arow[1], ap2 = arow[2], ap3 = arow[3];
        // b: 8 scalars, broadcast-packed
        float4 bv1 = *(const float4*)&Wsh[k * D + c1];
        float4 bv2 = *(const float4*)&Wsh[k * D + c2];
        ull b0 = bc2(bv1.x), b1 = bc2(bv1.y), b2 = bc2(bv1.z), b3 = bc2(bv1.w);
        ull b4 = bc2(bv2.x), b5 = bc2(bv2.y), b6 = bc2(bv2.z), b7 = bc2(bv2.w);

        fma2(acc[0][0], ap0, b0); fma2(acc[0][1], ap0, b1);
        fma2(acc[0][2], ap0, b2); fma2(acc[0][3], ap0, b3);
        fma2(acc[0][4], ap0, b4); fma2(acc[0][5], ap0, b5);
        fma2(acc[0][6], ap0, b6); fma2(acc[0][7], ap0, b7);
        fma2(acc[1][0], ap1, b0); fma2(acc[1][1], ap1, b1);
        fma2(acc[1][2], ap1, b2); fma2(acc[1][3], ap1, b3);
        fma2(acc[1][4], ap1, b4); fma2(acc[1][5], ap1, b5);
        fma2(acc[1][6], ap1, b6); fma2(acc[1][7], ap1, b7);
        fma2(acc[2][0], ap2, b0); fma2(acc[2][1], ap2, b1);
        fma2(acc[2][2], ap2, b2); fma2(acc[2][3], ap2, b3);
        fma2(acc[2][4], ap2, b4); fma2(acc[2][5], ap2, b5);
        fma2(acc[2][6], ap2, b6); fma2(acc[2][7], ap2, b7);
        fma2(acc[3][0], ap3, b0); fma2(acc[3][1], ap3, b1);
        fma2(acc[3][2], ap3, b2); fma2(acc[3][3], ap3, b3);
        fma2(acc[3][4], ap3, b4); fma2(acc[3][5], ap3, b5);
        fma2(acc[3][6], ap3, b6); fma2(acc[3][7], ap3, b7);
    }

    // Epilogue: unpack row-pairs and store two float4 per row
    #pragma unroll
    for (int i = 0; i < 4; i++) {
        float lo[8], hi[8];
        #pragma unroll
        for (int j = 0; j < 8; j++) upk2(lo[j], hi[j], acc[i][j]);

        int gr0 = row0 + rbase + 2 * i;
        if (gr0 < M) {
            float* o = g_support + (size_t)gr0 * D;
            *(float4*)(o + c1) = make_float4(lo[0], lo[1], lo[2], lo[3]);
            *(float4*)(o + c2) = make_float4(lo[4], lo[5], lo[6], lo[7]);
        }
        int gr1 = gr0 + 1;
        if (gr1 < M) {
            float* o = g_support + (size_t)gr1 * D;
            *(float4*)(o + c1) = make_float4(hi[0], hi[1], hi[2], hi[3]);
            *(float4*)(o + c2) = make_float4(hi[4], hi[5], hi[6], hi[7]);
        }
    }
}

// ---------------------------------------------------------------------------
// Counting-sort pipeline
// ---------------------------------------------------------------------------
__global__ void zero_count_kernel(int M) {
    int i = blockIdx.x * blockDim.x + threadIdx.x;
    if (i < M) g_cursor[i] = 0;
}

__global__ void hist_kernel(const void* __restrict__ er, int E) {
    int e = blockIdx.x * blockDim.x + threadIdx.x;
    if (e < E) atomicAdd(&g_cursor[load_idx(er, e)], 1);
}

__global__ void scan1_kernel(int M) {
    __shared__ int s[SCAN_T];
    int t = threadIdx.x;
    int i = blockIdx.x * SCAN_T + t;
    s[t] = (i < M) ? g_cursor[i] : 0;
    __syncthreads();
    #pragma unroll
    for (int off = SCAN_T / 2; off > 0; off >>= 1) {
        if (t < off) s[t] += s[t + off];
        __syncthreads();
    }
    if (t == 0) g_bsum[blockIdx.x] = s[0];
}

__global__ void scan2_kernel(int NB) {
    __shared__ int s[SCAN_T];
    int t = threadIdx.x;
    int v0 = (t < NB) ? g_bsum[t] : 0;
    s[t] = v0;
    __syncthreads();
    #pragma unroll
    for (int off = 1; off < SCAN_T; off <<= 1) {
        int v = (t >= off) ? s[t - off] : 0;
        __syncthreads();
        s[t] += v;
        __syncthreads();
    }
    if (t < NB) g_boff[t] = s[t] - v0;
}

__global__ void scan3_kernel(int M) {
    __shared__ int s[SCAN_T];
    int t = threadIdx.x;
    int i = blockIdx.x * SCAN_T + t;
    int v0 = (i < M) ? g_cursor[i] : 0;
    s[t] = v0;
    __syncthreads();
    #pragma unroll
    for (int off = 1; off < SCAN_T; off <<= 1) {
        int v = (t >= off) ? s[t - off] : 0;
        __syncthreads();
        s[t] += v;
        __syncthreads();
    }
    if (i < M) g_cursor[i] = g_boff[blockIdx.x] + s[t] - v0;
}

__global__ void reorder_kernel(const float* __restrict__ ew,
                               const void* __restrict__ er,
                               const void* __restrict__ ec, int E) {
    int e = blockIdx.x * blockDim.x + threadIdx.x;
    if (e >= E) return;
    int row = load_idx(er, e);
    int col = load_idx(ec, e);
    int pos = atomicAdd(&g_cursor[row], 1);
    g_scol[pos] = col;
    g_sw[pos]   = ew[e];
}

// ---------------------------------------------------------------------------
// Segmented accumulate: one warp per node, no atomics.
// ---------------------------------------------------------------------------
__global__ void __launch_bounds__(256)
segment_kernel(const float* __restrict__ bias, float* __restrict__ out, int M) {
    int n = (blockIdx.x * blockDim.x + threadIdx.x) >> 5;
    int lane = threadIdx.x & 31;
    if (n >= M) return;

    int start = (n == 0) ? 0 : g_cursor[n - 1];
    int end   = g_cursor[n];

    float4 acc = ((const float4*)bias)[lane];

    int e = start;
    for (; e + 4 <= end; e += 4) {
        int   c0 = g_scol[e],   c1 = g_scol[e+1], c2 = g_scol[e+2], c3 = g_scol[e+3];
        float w0 = g_sw[e],     w1 = g_sw[e+1],   w2 = g_sw[e+2],   w3 = g_sw[e+3];
        float4 s0 = *(const float4*)(g_support + (size_t)c0 * D + lane * 4);
        float4 s1 = *(const float4*)(g_support + (size_t)c1 * D + lane * 4);
        float4 s2 = *(const float4*)(g_support + (size_t)c2 * D + lane * 4);
        float4 s3 = *(const float4*)(g_support + (size_t)c3 * D + lane * 4);
        acc.x = fmaf(w0, s0.x, acc.x); acc.y = fmaf(w0, s0.y, acc.y);
        acc.z = fmaf(w0, s0.z, acc.z); acc.w = fmaf(w0, s0.w, acc.w);
        acc.x = fmaf(w1, s1.x, acc.x); acc.y = fmaf(w1, s1.y, acc.y);
        acc.z = fmaf(w1, s1.z, acc.z); acc.w = fmaf(w1, s1.w, acc.w);
        acc.x = fmaf(w2, s2.x, acc.x); acc.y = fmaf(w2, s2.y, acc.y);
        acc.z = fmaf(w2, s2.z, acc.z); acc.w = fmaf(w2, s2.w, acc.w);
        acc.x = fmaf(w3, s3.x, acc.x); acc.y = fmaf(w3, s3.y, acc.y);
        acc.z = fmaf(w3, s3.z, acc.z); acc.w = fmaf(w3, s3.w, acc.w);
    }
    for (; e < end; e++) {
        int   c0 = g_scol[e];
        float w0 = g_sw[e];
        float4 s0 = *(const float4*)(g_support + (size_t)c0 * D + lane * 4);
        acc.x = fmaf(w0, s0.x, acc.x); acc.y = fmaf(w0, s0.y, acc.y);
        acc.z = fmaf(w0, s0.z, acc.z); acc.w = fmaf(w0, s0.w, acc.w);
    }

    ((float4*)(out + (size_t)n * D))[lane] = acc;
}

// ---------------------------------------------------------------------------
extern "C" void kernel_launch(void* const* d_in, const int* in_sizes, int n_in,
                              void* d_out, int out_size) {
    const float* x    = (const float*)d_in[0];
    const float* w    = (const float*)d_in[1];
    const float* bias = (const float*)d_in[2];
    const float* ew   = (const float*)d_in[3];
    const void*  er   = d_in[4];
    const void*  ec   = d_in[5];
    float* out = (float*)d_out;

    int M = in_sizes[0] / D;           // 50000
    int E = in_sizes[3];               // 800000
    int NB = (M + SCAN_T - 1) / SCAN_T;

    const int gemm_smem = (D * D + D * 132) * (int)sizeof(float);
    cudaFuncSetAttribute(gemm_kernel,
                         cudaFuncAttributeMaxDynamicSharedMemorySize, gemm_smem);

    // One-time side-stream + events (host objects, not device memory; every
    // call issues the identical launch pattern — deterministic).
    static cudaStream_t s2 = nullptr;
    static cudaEvent_t evFork = nullptr, evJoin = nullptr;
    if (!s2) {
        cudaStreamCreateWithFlags(&s2, cudaStreamNonBlocking);
        cudaEventCreateWithFlags(&evFork, cudaEventDisableTiming);
        cudaEventCreateWithFlags(&evJoin, cudaEventDisableTiming);
    }

    // Fork: sort pipeline on s2, GEMM on the main (captured) stream.
    cudaEventRecord(evFork, 0);
    cudaStreamWaitEvent(s2, evFork, 0);

    detect_idx_kernel<<<1, 1, 0, s2>>>(er);
    zero_count_kernel<<<(M + 255) / 256, 256, 0, s2>>>(M);
    hist_kernel<<<(E + 255) / 256, 256, 0, s2>>>(er, E);
    scan1_kernel<<<NB, SCAN_T, 0, s2>>>(M);
    scan2_kernel<<<1, SCAN_T, 0, s2>>>(NB);
    scan3_kernel<<<NB, SCAN_T, 0, s2>>>(M);
    reorder_kernel<<<(E + 255) / 256, 256, 0, s2>>>(ew, er, ec, E);

    gemm_kernel<<<(M + BM - 1) / BM, 256, gemm_smem>>>(x, w, M);

    // Join: segment needs both g_support and the sorted edge lists.
    cudaEventRecord(evJoin, s2);
    cudaStreamWaitEvent(0, evJoin, 0);

    segment_kernel<<<(M + 7) / 8, 256>>>(bias, out, M);
}

// round 6
// speedup vs baseline: 1.7606x; 1.7606x over previous
#include <cuda_runtime.h>
#include <cuda_bf16.h>
#include <stdint.h>

#define D 128
#define MAX_NODES 50000
#define MAX_EDGES 800000
#define SCAN_T 256

typedef unsigned long long ull;

// ---- device scratch (no allocations allowed) ----
__device__ float g_support[(size_t)MAX_NODES * D];   // x @ W
__device__ int   g_cursor[MAX_NODES];                // counts -> starts -> ends
__device__ int   g_bsum[(MAX_NODES + SCAN_T - 1) / SCAN_T];
__device__ int   g_boff[(MAX_NODES + SCAN_T - 1) / SCAN_T];
__device__ int   g_scol[MAX_EDGES];
__device__ float g_sw[MAX_EDGES];
__device__ int   g_idx64;
// W transposed + split to bf16 hi/lo: Bt[n][k] (k contiguous), 128x128 bf16
__device__ uint4 g_bt_hi[2048];
__device__ uint4 g_bt_lo[2048];

// ===========================================================================
// helpers
// ===========================================================================
__device__ __forceinline__ uint32_t smem_u32(const void* p) {
    uint32_t a;
    asm("{ .reg .u64 t; cvta.to.shared.u64 t, %1; cvt.u32.u64 %0, t; }"
        : "=r"(a) : "l"(p));
    return a;
}
__device__ __forceinline__ uint32_t pack_bf16(float a, float b) {
    __nv_bfloat162 h = __floats2bfloat162_rn(a, b);
    return *(uint32_t*)&h;
}

#define LDSM_X4(r, a) \
    asm volatile("ldmatrix.sync.aligned.m8n8.x4.shared.b16 {%0,%1,%2,%3}, [%4];" \
                 : "=r"((r)[0]), "=r"((r)[1]), "=r"((r)[2]), "=r"((r)[3]) : "r"(a))
#define LDSM_X2(r, a) \
    asm volatile("ldmatrix.sync.aligned.m8n8.x2.shared.b16 {%0,%1}, [%2];" \
                 : "=r"((r)[0]), "=r"((r)[1]) : "r"(a))
#define MMA_BF16(d, a, b) \
    asm volatile("mma.sync.aligned.m16n8k16.row.col.f32.bf16.bf16.f32 " \
                 "{%0,%1,%2,%3}, {%4,%5,%6,%7}, {%8,%9}, {%0,%1,%2,%3};" \
                 : "+f"((d)[0]), "+f"((d)[1]), "+f"((d)[2]), "+f"((d)[3]) \
                 : "r"((a)[0]), "r"((a)[1]), "r"((a)[2]), "r"((a)[3]), \
                   "r"((b)[0]), "r"((b)[1]))

// ===========================================================================
// W convert+transpose+split: Bt_hi/lo[n][k] = split(W[k][n])
// ===========================================================================
__global__ void wconv_kernel(const float* __restrict__ w) {
    int idx = blockIdx.x * 256 + threadIdx.x;   // = k*128 + n
    if (idx >= D * D) return;
    int k = idx >> 7, n = idx & 127;
    float v = w[idx];
    __nv_bfloat16 h = __float2bfloat16(v);
    float r = v - __bfloat162float(h);
    __nv_bfloat16 l = __float2bfloat16(r);
    ((__nv_bfloat16*)g_bt_hi)[n * D + k] = h;
    ((__nv_bfloat16*)g_bt_lo)[n * D + k] = l;
}

// ===========================================================================
// mma.sync bf16 split-float GEMM: support[M,128] = x[M,128] @ W[128,128]
// 256 threads (8 warps) per CTA, 128 rows per CTA.
// Warp grid 4m x 2n; warp tile 32 rows x 64 cols.
// smem rows padded to 136 bf16 (272B) -> conflict-free ldmatrix.
// ===========================================================================
#define AS 136
#define MATE (128 * AS)                 // elements per smem matrix
__global__ void __launch_bounds__(256, 1)
gemm_mma_kernel(const float* __restrict__ x, int M) {
    extern __shared__ char smem[];
    __nv_bfloat16* Ahi = (__nv_bfloat16*)smem;
    __nv_bfloat16* Alo = Ahi + MATE;
    __nv_bfloat16* Bhi = Alo + MATE;
    __nv_bfloat16* Blo = Bhi + MATE;

    const int tid  = threadIdx.x;
    const int wid  = tid >> 5, lane = tid & 31;
    const int row0 = blockIdx.x * 128;

    // --- Stage B (pre-split, [n][k] 16B chunks) ---
    #pragma unroll
    for (int it = 0; it < 8; it++) {
        int idx = tid + 256 * it;               // 0..2047
        int n = idx >> 4, c = idx & 15;
        *(uint4*)(Bhi + n * AS + c * 8) = g_bt_hi[idx];
        *(uint4*)(Blo + n * AS + c * 8) = g_bt_lo[idx];
    }
    // --- Stage A: fp32 -> bf16 hi/lo split ---
    #pragma unroll
    for (int it = 0; it < 16; it++) {
        int idx = tid + 256 * it;               // 0..4095 float4s
        int r = idx >> 5, q = idx & 31;
        int gr = row0 + r;
        float4 v = make_float4(0.f, 0.f, 0.f, 0.f);
        if (gr < M) v = ((const float4*)(x + (size_t)gr * D))[q];
        float f[4] = {v.x, v.y, v.z, v.w};
        float hi[4], lo[4];
        #pragma unroll
        for (int j = 0; j < 4; j++) {
            __nv_bfloat16 h = __float2bfloat16(f[j]);
            hi[j] = __bfloat162float(h);
            lo[j] = f[j] - hi[j];
        }
        uint2 ph = make_uint2(pack_bf16(hi[0], hi[1]), pack_bf16(hi[2], hi[3]));
        uint2 pl = make_uint2(pack_bf16(lo[0], lo[1]), pack_bf16(lo[2], lo[3]));
        *(uint2*)(Ahi + r * AS + q * 4) = ph;
        *(uint2*)(Alo + r * AS + q * 4) = pl;
    }
    __syncthreads();

    const uint32_t sbA = smem_u32(Ahi);
    const uint32_t sbB = smem_u32(Bhi);
    const uint32_t HILO = MATE * 2;             // byte offset hi -> lo

    const int mwarp = wid >> 1, nwarp = wid & 1;
    const int mrow = mwarp * 32;
    const int ncol = nwarp * 64;

    float acc[2][8][4];
    #pragma unroll
    for (int mt = 0; mt < 2; mt++)
        #pragma unroll
        for (int nt = 0; nt < 8; nt++)
            #pragma unroll
            for (int q = 0; q < 4; q++) acc[mt][nt][q] = 0.f;

    // ldmatrix lane addressing
    const int aRow = (lane & 15), aKg = (lane >> 4);          // A: x4
    const int bN   = (lane & 7),  bKg = ((lane >> 3) & 1);    // B: x2

    #pragma unroll
    for (int ks = 0; ks < 8; ks++) {
        const int k0 = ks * 16;
        uint32_t ahi[2][4], alo[2][4];
        #pragma unroll
        for (int mt = 0; mt < 2; mt++) {
            uint32_t aaddr = sbA + (uint32_t)((mrow + mt * 16 + aRow) * 272
                                              + (k0 + aKg * 8) * 2);
            LDSM_X4(ahi[mt], aaddr);
            LDSM_X4(alo[mt], aaddr + HILO);
        }
        #pragma unroll
        for (int nt = 0; nt < 8; nt++) {
            uint32_t baddr = sbB + (uint32_t)((ncol + nt * 8 + bN) * 272
                                              + (k0 + bKg * 8) * 2);
            uint32_t bhi[2], blo[2];
            LDSM_X2(bhi, baddr);
            LDSM_X2(blo, baddr + HILO);
            #pragma unroll
            for (int mt = 0; mt < 2; mt++) {
                MMA_BF16(acc[mt][nt], ahi[mt], bhi);
                MMA_BF16(acc[mt][nt], ahi[mt], blo);
                MMA_BF16(acc[mt][nt], alo[mt], bhi);
            }
        }
    }

    // --- Epilogue: write fp32 support directly ---
    const int erow = (lane >> 2);               // 0..7
    const int ecol = (lane & 3) * 2;
    #pragma unroll
    for (int mt = 0; mt < 2; mt++) {
        #pragma unroll
        for (int nt = 0; nt < 8; nt++) {
            int r0 = row0 + mrow + mt * 16 + erow;
            int c  = ncol + nt * 8 + ecol;
            if (r0 < M)
                *(float2*)(g_support + (size_t)r0 * D + c) =
                    make_float2(acc[mt][nt][0], acc[mt][nt][1]);
            if (r0 + 8 < M)
                *(float2*)(g_support + (size_t)(r0 + 8) * D + c) =
                    make_float2(acc[mt][nt][2], acc[mt][nt][3]);
        }
    }
}

// ===========================================================================
// Index detect + counting-sort pipeline (unchanged from round 3)
// ===========================================================================
__global__ void detect_idx_kernel(const void* idx) {
    const ull* p = (const ull*)idx;
    int is64 = 1;
    #pragma unroll
    for (int i = 0; i < 16; i++)
        if (p[i] >= (1ULL << 32)) is64 = 0;
    g_idx64 = is64;
}
__device__ __forceinline__ int load_idx(const void* buf, int e) {
    return g_idx64 ? (int)((const long long*)buf)[e] : ((const int*)buf)[e];
}
__global__ void zero_count_kernel(int M) {
    int i = blockIdx.x * blockDim.x + threadIdx.x;
    if (i < M) g_cursor[i] = 0;
}
__global__ void hist_kernel(const void* __restrict__ er, int E) {
    int e = blockIdx.x * blockDim.x + threadIdx.x;
    if (e < E) atomicAdd(&g_cursor[load_idx(er, e)], 1);
}
__global__ void scan1_kernel(int M) {
    __shared__ int s[SCAN_T];
    int t = threadIdx.x, i = blockIdx.x * SCAN_T + t;
    s[t] = (i < M) ? g_cursor[i] : 0;
    __syncthreads();
    #pragma unroll
    for (int off = SCAN_T / 2; off > 0; off >>= 1) {
        if (t < off) s[t] += s[t + off];
        __syncthreads();
    }
    if (t == 0) g_bsum[blockIdx.x] = s[0];
}
__global__ void scan2_kernel(int NB) {
    __shared__ int s[SCAN_T];
    int t = threadIdx.x;
    int v0 = (t < NB) ? g_bsum[t] : 0;
    s[t] = v0;
    __syncthreads();
    #pragma unroll
    for (int off = 1; off < SCAN_T; off <<= 1) {
        int v = (t >= off) ? s[t - off] : 0;
        __syncthreads();
        s[t] += v;
        __syncthreads();
    }
    if (t < NB) g_boff[t] = s[t] - v0;
}
__global__ void scan3_kernel(int M) {
    __shared__ int s[SCAN_T];
    int t = threadIdx.x, i = blockIdx.x * SCAN_T + t;
    int v0 = (i < M) ? g_cursor[i] : 0;
    s[t] = v0;
    __syncthreads();
    #pragma unroll
    for (int off = 1; off < SCAN_T; off <<= 1) {
        int v = (t >= off) ? s[t - off] : 0;
        __syncthreads();
        s[t] += v;
        __syncthreads();
    }
    if (i < M) g_cursor[i] = g_boff[blockIdx.x] + s[t] - v0;
}
__global__ void reorder_kernel(const float* __restrict__ ew,
                               const void* __restrict__ er,
                               const void* __restrict__ ec, int E) {
    int e = blockIdx.x * blockDim.x + threadIdx.x;
    if (e >= E) return;
    int row = load_idx(er, e);
    int col = load_idx(ec, e);
    int pos = atomicAdd(&g_cursor[row], 1);
    g_scol[pos] = col;
    g_sw[pos]   = ew[e];
}

// ---------------------------------------------------------------------------
// Segmented accumulate: one warp per node, no atomics.
// ---------------------------------------------------------------------------
__global__ void __launch_bounds__(256)
segment_kernel(const float* __restrict__ bias, float* __restrict__ out, int M) {
    int n = (blockIdx.x * blockDim.x + threadIdx.x) >> 5;
    int lane = threadIdx.x & 31;
    if (n >= M) return;

    int start = (n == 0) ? 0 : g_cursor[n - 1];
    int end   = g_cursor[n];

    float4 acc = ((const float4*)bias)[lane];

    int e = start;
    for (; e + 4 <= end; e += 4) {
        int   c0 = g_scol[e],   c1 = g_scol[e+1], c2 = g_scol[e+2], c3 = g_scol[e+3];
        float w0 = g_sw[e],     w1 = g_sw[e+1],   w2 = g_sw[e+2],   w3 = g_sw[e+3];
        float4 s0 = *(const float4*)(g_support + (size_t)c0 * D + lane * 4);
        float4 s1 = *(const float4*)(g_support + (size_t)c1 * D + lane * 4);
        float4 s2 = *(const float4*)(g_support + (size_t)c2 * D + lane * 4);
        float4 s3 = *(const float4*)(g_support + (size_t)c3 * D + lane * 4);
        acc.x = fmaf(w0, s0.x, acc.x); acc.y = fmaf(w0, s0.y, acc.y);
        acc.z = fmaf(w0, s0.z, acc.z); acc.w = fmaf(w0, s0.w, acc.w);
        acc.x = fmaf(w1, s1.x, acc.x); acc.y = fmaf(w1, s1.y, acc.y);
        acc.z = fmaf(w1, s1.z, acc.z); acc.w = fmaf(w1, s1.w, acc.w);
        acc.x = fmaf(w2, s2.x, acc.x); acc.y = fmaf(w2, s2.y, acc.y);
        acc.z = fmaf(w2, s2.z, acc.z); acc.w = fmaf(w2, s2.w, acc.w);
        acc.x = fmaf(w3, s3.x, acc.x); acc.y = fmaf(w3, s3.y, acc.y);
        acc.z = fmaf(w3, s3.z, acc.z); acc.w = fmaf(w3, s3.w, acc.w);
    }
    for (; e < end; e++) {
        int   c0 = g_scol[e];
        float w0 = g_sw[e];
        float4 s0 = *(const float4*)(g_support + (size_t)c0 * D + lane * 4);
        acc.x = fmaf(w0, s0.x, acc.x); acc.y = fmaf(w0, s0.y, acc.y);
        acc.z = fmaf(w0, s0.z, acc.z); acc.w = fmaf(w0, s0.w, acc.w);
    }

    ((float4*)(out + (size_t)n * D))[lane] = acc;
}

// ---------------------------------------------------------------------------
extern "C" void kernel_launch(void* const* d_in, const int* in_sizes, int n_in,
                              void* d_out, int out_size) {
    const float* x    = (const float*)d_in[0];
    const float* w    = (const float*)d_in[1];
    const float* bias = (const float*)d_in[2];
    const float* ew   = (const float*)d_in[3];
    const void*  er   = d_in[4];
    const void*  ec   = d_in[5];
    float* out = (float*)d_out;

    int M = in_sizes[0] / D;           // 50000
    int E = in_sizes[3];               // 800000
    int NB = (M + SCAN_T - 1) / SCAN_T;

    const int mma_smem = 4 * MATE * (int)sizeof(__nv_bfloat16);   // 139264
    cudaFuncSetAttribute(gemm_mma_kernel,
                         cudaFuncAttributeMaxDynamicSharedMemorySize, mma_smem);

    detect_idx_kernel<<<1, 1>>>(er);
    wconv_kernel<<<(D * D + 255) / 256, 256>>>(w);

    gemm_mma_kernel<<<(M + 127) / 128, 256, mma_smem>>>(x, M);

    zero_count_kernel<<<(M + 255) / 256, 256>>>(M);
    hist_kernel<<<(E + 255) / 256, 256>>>(er, E);
    scan1_kernel<<<NB, SCAN_T>>>(M);
    scan2_kernel<<<1, SCAN_T>>>(NB);
    scan3_kernel<<<NB, SCAN_T>>>(M);
    reorder_kernel<<<(E + 255) / 256, 256>>>(ew, er, ec, E);

    segment_kernel<<<(M + 7) / 8, 256>>>(bias, out, M);
}

// round 8
// speedup vs baseline: 1.9641x; 1.1156x over previous
#include <cuda_runtime.h>
#include <cuda_bf16.h>
#include <stdint.h>

#define D 128
#define MAX_NODES 50000
#define MAX_EDGES 800000
#define SCAN_T 256

typedef unsigned long long ull;

// ---- device scratch (no allocations allowed) ----
__device__ float g_support[(size_t)MAX_NODES * D];   // x @ W
__device__ int   g_cursor[MAX_NODES];                // counts -> starts -> ends
__device__ int   g_bsum[(MAX_NODES + SCAN_T - 1) / SCAN_T];
__device__ int   g_boff[(MAX_NODES + SCAN_T - 1) / SCAN_T];
__device__ int   g_scol[MAX_EDGES];
__device__ float g_sw[MAX_EDGES];
__device__ int   g_idx64;
// W transposed + split to bf16 hi/lo: Bt[n][k] (k contiguous), 128x128 bf16
__device__ uint4 g_bt_hi[2048];
__device__ uint4 g_bt_lo[2048];

// ===========================================================================
// helpers
// ===========================================================================
__device__ __forceinline__ uint32_t smem_u32(const void* p) {
    uint32_t a;
    asm("{ .reg .u64 t; cvta.to.shared.u64 t, %1; cvt.u32.u64 %0, t; }"
        : "=r"(a) : "l"(p));
    return a;
}
__device__ __forceinline__ uint32_t pack_bf16(float a, float b) {
    __nv_bfloat162 h = __floats2bfloat162_rn(a, b);
    return *(uint32_t*)&h;
}

#define LDSM_X4(r, a) \
    asm volatile("ldmatrix.sync.aligned.m8n8.x4.shared.b16 {%0,%1,%2,%3}, [%4];" \
                 : "=r"((r)[0]), "=r"((r)[1]), "=r"((r)[2]), "=r"((r)[3]) : "r"(a))
#define LDSM_X2(r, a) \
    asm volatile("ldmatrix.sync.aligned.m8n8.x2.shared.b16 {%0,%1}, [%2];" \
                 : "=r"((r)[0]), "=r"((r)[1]) : "r"(a))
#define MMA_BF16(d, a, b) \
    asm volatile("mma.sync.aligned.m16n8k16.row.col.f32.bf16.bf16.f32 " \
                 "{%0,%1,%2,%3}, {%4,%5,%6,%7}, {%8,%9}, {%0,%1,%2,%3};" \
                 : "+f"((d)[0]), "+f"((d)[1]), "+f"((d)[2]), "+f"((d)[3]) \
                 : "r"((a)[0]), "r"((a)[1]), "r"((a)[2]), "r"((a)[3]), \
                   "r"((b)[0]), "r"((b)[1]))

// ===========================================================================
// W convert+transpose+split: Bt_hi/lo[n][k] = split(W[k][n])
// ===========================================================================
__global__ void wconv_kernel(const float* __restrict__ w) {
    int idx = blockIdx.x * 256 + threadIdx.x;   // = k*128 + n
    if (idx >= D * D) return;
    int k = idx >> 7, n = idx & 127;
    float v = w[idx];
    __nv_bfloat16 h = __float2bfloat16(v);
    float r = v - __bfloat162float(h);
    __nv_bfloat16 l = __float2bfloat16(r);
    ((__nv_bfloat16*)g_bt_hi)[n * D + k] = h;
    ((__nv_bfloat16*)g_bt_lo)[n * D + k] = l;
}

// ===========================================================================
// mma.sync bf16 split-float GEMM: support[M,128] = x[M,128] @ W[128,128]
// (identical to round 6)
// ===========================================================================
#define AS 136
#define MATE (128 * AS)                 // elements per smem matrix
__global__ void __launch_bounds__(256, 1)
gemm_mma_kernel(const float* __restrict__ x, int M) {
    extern __shared__ char smem[];
    __nv_bfloat16* Ahi = (__nv_bfloat16*)smem;
    __nv_bfloat16* Alo = Ahi + MATE;
    __nv_bfloat16* Bhi = Alo + MATE;
    __nv_bfloat16* Blo = Bhi + MATE;

    const int tid  = threadIdx.x;
    const int wid  = tid >> 5, lane = tid & 31;
    const int row0 = blockIdx.x * 128;

    #pragma unroll
    for (int it = 0; it < 8; it++) {
        int idx = tid + 256 * it;               // 0..2047
        int n = idx >> 4, c = idx & 15;
        *(uint4*)(Bhi + n * AS + c * 8) = g_bt_hi[idx];
        *(uint4*)(Blo + n * AS + c * 8) = g_bt_lo[idx];
    }
    #pragma unroll
    for (int it = 0; it < 16; it++) {
        int idx = tid + 256 * it;               // 0..4095 float4s
        int r = idx >> 5, q = idx & 31;
        int gr = row0 + r;
        float4 v = make_float4(0.f, 0.f, 0.f, 0.f);
        if (gr < M) v = ((const float4*)(x + (size_t)gr * D))[q];
        float f[4] = {v.x, v.y, v.z, v.w};
        float hi[4], lo[4];
        #pragma unroll
        for (int j = 0; j < 4; j++) {
            __nv_bfloat16 h = __float2bfloat16(f[j]);
            hi[j] = __bfloat162float(h);
            lo[j] = f[j] - hi[j];
        }
        uint2 ph = make_uint2(pack_bf16(hi[0], hi[1]), pack_bf16(hi[2], hi[3]));
        uint2 pl = make_uint2(pack_bf16(lo[0], lo[1]), pack_bf16(lo[2], lo[3]));
        *(uint2*)(Ahi + r * AS + q * 4) = ph;
        *(uint2*)(Alo + r * AS + q * 4) = pl;
    }
    __syncthreads();

    const uint32_t sbA = smem_u32(Ahi);
    const uint32_t sbB = smem_u32(Bhi);
    const uint32_t HILO = MATE * 2;             // byte offset hi -> lo

    const int mwarp = wid >> 1, nwarp = wid & 1;
    const int mrow = mwarp * 32;
    const int ncol = nwarp * 64;

    float acc[2][8][4];
    #pragma unroll
    for (int mt = 0; mt < 2; mt++)
        #pragma unroll
        for (int nt = 0; nt < 8; nt++)
            #pragma unroll
            for (int q = 0; q < 4; q++) acc[mt][nt][q] = 0.f;

    const int aRow = (lane & 15), aKg = (lane >> 4);
    const int bN   = (lane & 7),  bKg = ((lane >> 3) & 1);

    #pragma unroll
    for (int ks = 0; ks < 8; ks++) {
        const int k0 = ks * 16;
        uint32_t ahi[2][4], alo[2][4];
        #pragma unroll
        for (int mt = 0; mt < 2; mt++) {
            uint32_t aaddr = sbA + (uint32_t)((mrow + mt * 16 + aRow) * 272
                                              + (k0 + aKg * 8) * 2);
            LDSM_X4(ahi[mt], aaddr);
            LDSM_X4(alo[mt], aaddr + HILO);
        }
        #pragma unroll
        for (int nt = 0; nt < 8; nt++) {
            uint32_t baddr = sbB + (uint32_t)((ncol + nt * 8 + bN) * 272
                                              + (k0 + bKg * 8) * 2);
            uint32_t bhi[2], blo[2];
            LDSM_X2(bhi, baddr);
            LDSM_X2(blo, baddr + HILO);
            #pragma unroll
            for (int mt = 0; mt < 2; mt++) {
                MMA_BF16(acc[mt][nt], ahi[mt], bhi);
                MMA_BF16(acc[mt][nt], ahi[mt], blo);
                MMA_BF16(acc[mt][nt], alo[mt], bhi);
            }
        }
    }

    const int erow = (lane >> 2);
    const int ecol = (lane & 3) * 2;
    #pragma unroll
    for (int mt = 0; mt < 2; mt++) {
        #pragma unroll
        for (int nt = 0; nt < 8; nt++) {
            int r0 = row0 + mrow + mt * 16 + erow;
            int c  = ncol + nt * 8 + ecol;
            if (r0 < M)
                *(float2*)(g_support + (size_t)r0 * D + c) =
                    make_float2(acc[mt][nt][0], acc[mt][nt][1]);
            if (r0 + 8 < M)
                *(float2*)(g_support + (size_t)(r0 + 8) * D + c) =
                    make_float2(acc[mt][nt][2], acc[mt][nt][3]);
        }
    }
}

// ===========================================================================
// Sort pipeline. zero_count also does the index-width detect (block 0).
// ===========================================================================
__global__ void zero_count_kernel(const void* __restrict__ er, int M) {
    int i = blockIdx.x * blockDim.x + threadIdx.x;
    if (i < M) g_cursor[i] = 0;
    if (blockIdx.x == 0 && threadIdx.x == 0) {
        const ull* p = (const ull*)er;
        int is64 = 1;
        #pragma unroll
        for (int j = 0; j < 16; j++)
            if (p[j] >= (1ULL << 32)) is64 = 0;
        g_idx64 = is64;
    }
}
__device__ __forceinline__ int load_idx(const void* buf, int e) {
    return g_idx64 ? (int)((const long long*)buf)[e] : ((const int*)buf)[e];
}
__global__ void hist_kernel(const void* __restrict__ er, int E) {
    int e = blockIdx.x * blockDim.x + threadIdx.x;
    if (e < E) atomicAdd(&g_cursor[load_idx(er, e)], 1);
}
__global__ void scan1_kernel(int M) {
    __shared__ int s[SCAN_T];
    int t = threadIdx.x, i = blockIdx.x * SCAN_T + t;
    s[t] = (i < M) ? g_cursor[i] : 0;
    __syncthreads();
    #pragma unroll
    for (int off = SCAN_T / 2; off > 0; off >>= 1) {
        if (t < off) s[t] += s[t + off];
        __syncthreads();
    }
    if (t == 0) g_bsum[blockIdx.x] = s[0];
}
__global__ void scan2_kernel(int NB) {
    __shared__ int s[SCAN_T];
    int t = threadIdx.x;
    int v0 = (t < NB) ? g_bsum[t] : 0;
    s[t] = v0;
    __syncthreads();
    #pragma unroll
    for (int off = 1; off < SCAN_T; off <<= 1) {
        int v = (t >= off) ? s[t - off] : 0;
        __syncthreads();
        s[t] += v;
        __syncthreads();
    }
    if (t < NB) g_boff[t] = s[t] - v0;
}
__global__ void scan3_kernel(int M) {
    __shared__ int s[SCAN_T];
    int t = threadIdx.x, i = blockIdx.x * SCAN_T + t;
    int v0 = (i < M) ? g_cursor[i] : 0;
    s[t] = v0;
    __syncthreads();
    #pragma unroll
    for (int off = 1; off < SCAN_T; off <<= 1) {
        int v = (t >= off) ? s[t - off] : 0;
        __syncthreads();
        s[t] += v;
        __syncthreads();
    }
    if (i < M) g_cursor[i] = g_boff[blockIdx.x] + s[t] - v0;
}
__global__ void reorder_kernel(const float* __restrict__ ew,
                               const void* __restrict__ er,
                               const void* __restrict__ ec, int E) {
    int e = blockIdx.x * blockDim.x + threadIdx.x;
    if (e >= E) return;
    int row = load_idx(er, e);
    int col = load_idx(ec, e);
    int pos = atomicAdd(&g_cursor[row], 1);
    g_scol[pos] = col;
    g_sw[pos]   = ew[e];
}

// ---------------------------------------------------------------------------
// Segmented accumulate: one warp per node, no atomics.
// ---------------------------------------------------------------------------
__global__ void __launch_bounds__(256)
segment_kernel(const float* __restrict__ bias, float* __restrict__ out, int M) {
    int n = (blockIdx.x * blockDim.x + threadIdx.x) >> 5;
    int lane = threadIdx.x & 31;
    if (n >= M) return;

    int start = (n == 0) ? 0 : g_cursor[n - 1];
    int end   = g_cursor[n];

    float4 acc = ((const float4*)bias)[lane];

    int e = start;
    for (; e + 4 <= end; e += 4) {
        int   c0 = g_scol[e],   c1 = g_scol[e+1], c2 = g_scol[e+2], c3 = g_scol[e+3];
        float w0 = g_sw[e],     w1 = g_sw[e+1],   w2 = g_sw[e+2],   w3 = g_sw[e+3];
        float4 s0 = *(const float4*)(g_support + (size_t)c0 * D + lane * 4);
        float4 s1 = *(const float4*)(g_support + (size_t)c1 * D + lane * 4);
        float4 s2 = *(const float4*)(g_support + (size_t)c2 * D + lane * 4);
        float4 s3 = *(const float4*)(g_support + (size_t)c3 * D + lane * 4);
        acc.x = fmaf(w0, s0.x, acc.x); acc.y = fmaf(w0, s0.y, acc.y);
        acc.z = fmaf(w0, s0.z, acc.z); acc.w = fmaf(w0, s0.w, acc.w);
        acc.x = fmaf(w1, s1.x, acc.x); acc.y = fmaf(w1, s1.y, acc.y);
        acc.z = fmaf(w1, s1.z, acc.z); acc.w = fmaf(w1, s1.w, acc.w);
        acc.x = fmaf(w2, s2.x, acc.x); acc.y = fmaf(w2, s2.y, acc.y);
        acc.z = fmaf(w2, s2.z, acc.z); acc.w = fmaf(w2, s2.w, acc.w);
        acc.x = fmaf(w3, s3.x, acc.x); acc.y = fmaf(w3, s3.y, acc.y);
        acc.z = fmaf(w3, s3.z, acc.z); acc.w = fmaf(w3, s3.w, acc.w);
    }
    for (; e < end; e++) {
        int   c0 = g_scol[e];
        float w0 = g_sw[e];
        float4 s0 = *(const float4*)(g_support + (size_t)c0 * D + lane * 4);
        acc.x = fmaf(w0, s0.x, acc.x); acc.y = fmaf(w0, s0.y, acc.y);
        acc.z = fmaf(w0, s0.z, acc.z); acc.w = fmaf(w0, s0.w, acc.w);
    }

    ((float4*)(out + (size_t)n * D))[lane] = acc;
}

// ---------------------------------------------------------------------------
extern "C" void kernel_launch(void* const* d_in, const int* in_sizes, int n_in,
                              void* d_out, int out_size) {
    const float* x    = (const float*)d_in[0];
    const float* w    = (const float*)d_in[1];
    const float* bias = (const float*)d_in[2];
    const float* ew   = (const float*)d_in[3];
    const void*  er   = d_in[4];
    const void*  ec   = d_in[5];
    float* out = (float*)d_out;

    int M = in_sizes[0] / D;           // 50000
    int E = in_sizes[3];               // 800000
    int NB = (M + SCAN_T - 1) / SCAN_T;

    const int mma_smem = 4 * MATE * (int)sizeof(__nv_bfloat16);   // 139264
    cudaFuncSetAttribute(gemm_mma_kernel,
                         cudaFuncAttributeMaxDynamicSharedMemorySize, mma_smem);

    // Side-stream + events for fork/join (host objects only; identical launch
    // pattern every call — deterministic and graph-capturable).
    static cudaStream_t s2 = nullptr;
    static cudaEvent_t evFork = nullptr, evJoin = nullptr;
    if (!s2) {
        cudaStreamCreateWithFlags(&s2, cudaStreamNonBlocking);
        cudaEventCreateWithFlags(&evFork, cudaEventDisableTiming);
        cudaEventCreateWithFlags(&evJoin, cudaEventDisableTiming);
    }

    // Fork: sort pipeline on s2, GEMM chain on the main stream.
    cudaEventRecord(evFork, 0);
    cudaStreamWaitEvent(s2, evFork, 0);

    zero_count_kernel<<<(M + 255) / 256, 256, 0, s2>>>(er, M);
    hist_kernel<<<(E + 255) / 256, 256, 0, s2>>>(er, E);
    scan1_kernel<<<NB, SCAN_T, 0, s2>>>(M);
    scan2_kernel<<<1, SCAN_T, 0, s2>>>(NB);
    scan3_kernel<<<NB, SCAN_T, 0, s2>>>(M);
    reorder_kernel<<<(E + 255) / 256, 256, 0, s2>>>(ew, er, ec, E);

    wconv_kernel<<<(D * D + 255) / 256, 256>>>(w);
    gemm_mma_kernel<<<(M + 127) / 128, 256, mma_smem>>>(x, M);

    // Join: segment needs g_support + sorted edges.
    cudaEventRecord(evJoin, s2);
    cudaStreamWaitEvent(0, evJoin, 0);

    segment_kernel<<<(M + 7) / 8, 256>>>(bias, out, M);
}